// round 11
// baseline (speedup 1.0000x reference)
#include <cuda_runtime.h>

#define NUM_GRAPHS 1024
#define TPB 256
#define NBLOCKS 740    // 148 SMs x 5 blocks/SM -> single wave
#define NWARPS_BLK (TPB / 32)

__device__ float        g_Sqr[NUM_GRAPHS * 3];   // sum q_i * r_i
__device__ float        g_Sr[NUM_GRAPHS * 3];    // sum r_i
__device__ double       g_sumq;
__device__ unsigned int g_count;

__device__ __forceinline__ void warp_reduce6(float& a0, float& a1, float& a2,
                                             float& a3, float& a4, float& a5) {
    #pragma unroll
    for (int s = 16; s > 0; s >>= 1) {
        a0 += __shfl_down_sync(0xffffffffu, a0, s);
        a1 += __shfl_down_sync(0xffffffffu, a1, s);
        a2 += __shfl_down_sync(0xffffffffu, a2, s);
        a3 += __shfl_down_sync(0xffffffffu, a3, s);
        a4 += __shfl_down_sync(0xffffffffu, a4, s);
        a5 += __shfl_down_sync(0xffffffffu, a5, s);
    }
}

__device__ __forceinline__ void atomic6(int seg,
                                        float ax, float ay, float az,
                                        float rx, float ry, float rz) {
    atomicAdd(&g_Sqr[seg * 3 + 0], ax);
    atomicAdd(&g_Sqr[seg * 3 + 1], ay);
    atomicAdd(&g_Sqr[seg * 3 + 2], az);
    atomicAdd(&g_Sr[seg * 3 + 0], rx);
    atomicAdd(&g_Sr[seg * 3 + 1], ry);
    atomicAdd(&g_Sr[seg * 3 + 2], rz);
}

__global__ __launch_bounds__(TPB, 5)
void polar_fused(const float* __restrict__ pos,
                 const float* __restrict__ q,
                 const int* __restrict__ batch,
                 float* __restrict__ out,
                 long long n, long long chunk, double inv_n) {
    __shared__ float q_sm[NWARPS_BLK][2][128];

    const int lane = threadIdx.x & 31;
    const int w    = threadIdx.x >> 5;
    const long long warpId = ((long long)blockIdx.x * blockDim.x + threadIdx.x) >> 5;
    const long long start  = warpId * chunk;

    float qs = 0.f;

    if (start < n) {
        long long end = start + chunk; if (end > n) end = n;
        const long long nE      = end - start;
        const long long nTiles  = nE >> 7;          // full 128-node tiles
        const long long tailBeg = start + (nTiles << 7);

        // coalesced bases: start is a multiple of 4 -> both 16B-aligned
        const float4* qp = reinterpret_cast<const float4*>(q + start);
        const float4* pp = reinterpret_cast<const float4*>(pos + start * 3);

        // precomputed iter-invariant q-index for each of this lane's 12 pos floats
        const int l4 = lane << 2;
        int nA[4], nB[4], nC[4];
        #pragma unroll
        for (int k = 0; k < 4; k++) {
            nA[k] = (l4 + k) / 3;
            nB[k] = (128 + l4 + k) / 3;
            nC[k] = (256 + l4 + k) / 3;
        }

        // rotated-space accumulators: s_j holds component (rot + j) % 3, rot = lane % 3
        float s0 = 0.f, s1 = 0.f, s2 = 0.f;       // sum r
        float w0 = 0.f, w1 = 0.f, w2 = 0.f;       // sum q*r
        const int rot = lane % 3;
        int curSeg = batch[start];

        for (long long j = 0; j < nTiles; j++) {
            const long long t0 = start + (j << 7);
            const int g0 = batch[t0];
            const int g1 = batch[t0 + 127];

            if (g0 == g1) {
                // ---- uniform tile: fully coalesced ----
                if (g0 != curSeg) {
                    // flush rotated accumulators for curSeg (warp-uniform)
                    float x  = (rot == 0) ? s0 : ((rot == 1) ? s2 : s1);
                    float y  = (rot == 0) ? s1 : ((rot == 1) ? s0 : s2);
                    float z  = (rot == 0) ? s2 : ((rot == 1) ? s1 : s0);
                    float wx = (rot == 0) ? w0 : ((rot == 1) ? w2 : w1);
                    float wy = (rot == 0) ? w1 : ((rot == 1) ? w0 : w2);
                    float wz = (rot == 0) ? w2 : ((rot == 1) ? w1 : w0);
                    warp_reduce6(wx, wy, wz, x, y, z);
                    if (lane == 0) atomic6(curSeg, wx, wy, wz, x, y, z);
                    s0 = s1 = s2 = w0 = w1 = w2 = 0.f;
                    curSeg = g0;
                }

                float4 qv = qp[(j << 5) + lane];
                float4 PA = pp[j * 96 + lane];
                float4 PB = pp[j * 96 + 32 + lane];
                float4 PC = pp[j * 96 + 64 + lane];

                float* qb = q_sm[w][j & 1];
                *reinterpret_cast<float4*>(&qb[l4]) = qv;
                __syncwarp();

                qs += (qv.x + qv.y) + (qv.z + qv.w);

                // A floats: slot k -> s[k%3]
                s0 += PA.x + PA.w;  s1 += PA.y;  s2 += PA.z;
                w0 = fmaf(qb[nA[0]], PA.x, w0);
                w1 = fmaf(qb[nA[1]], PA.y, w1);
                w2 = fmaf(qb[nA[2]], PA.z, w2);
                w0 = fmaf(qb[nA[3]], PA.w, w0);
                // B floats: slot k -> s[(k+2)%3]
                s2 += PB.x + PB.w;  s0 += PB.y;  s1 += PB.z;
                w2 = fmaf(qb[nB[0]], PB.x, w2);
                w0 = fmaf(qb[nB[1]], PB.y, w0);
                w1 = fmaf(qb[nB[2]], PB.z, w1);
                w2 = fmaf(qb[nB[3]], PB.w, w2);
                // C floats: slot k -> s[(k+1)%3]
                s1 += PC.x + PC.w;  s2 += PC.y;  s0 += PC.z;
                w1 = fmaf(qb[nC[0]], PC.x, w1);
                w2 = fmaf(qb[nC[1]], PC.y, w2);
                w0 = fmaf(qb[nC[2]], PC.z, w0);
                w1 = fmaf(qb[nC[3]], PC.w, w1);
            } else {
                // ---- boundary tile (~1.5%): flush, then per-lane scalar ----
                float x  = (rot == 0) ? s0 : ((rot == 1) ? s2 : s1);
                float y  = (rot == 0) ? s1 : ((rot == 1) ? s0 : s2);
                float z  = (rot == 0) ? s2 : ((rot == 1) ? s1 : s0);
                float wx = (rot == 0) ? w0 : ((rot == 1) ? w2 : w1);
                float wy = (rot == 0) ? w1 : ((rot == 1) ? w0 : w2);
                float wz = (rot == 0) ? w2 : ((rot == 1) ? w1 : w0);
                warp_reduce6(wx, wy, wz, x, y, z);
                if (lane == 0) atomic6(curSeg, wx, wy, wz, x, y, z);
                s0 = s1 = s2 = w0 = w1 = w2 = 0.f;

                int   cur = -1;
                float ax = 0.f, ay = 0.f, az = 0.f, rx = 0.f, ry = 0.f, rz = 0.f;
                #pragma unroll
                for (int k = 0; k < 4; k++) {
                    long long i = t0 + l4 + k;
                    int   g  = batch[i];
                    float qi = q[i];
                    float x1 = pos[i * 3 + 0], y1 = pos[i * 3 + 1], z1 = pos[i * 3 + 2];
                    if (g != cur) {
                        if (cur >= 0) atomic6(cur, ax, ay, az, rx, ry, rz);
                        ax = ay = az = rx = ry = rz = 0.f;
                        cur = g;
                    }
                    qs += qi;
                    ax = fmaf(qi, x1, ax); ay = fmaf(qi, y1, ay); az = fmaf(qi, z1, az);
                    rx += x1; ry += y1; rz += z1;
                }
                if (cur >= 0) atomic6(cur, ax, ay, az, rx, ry, rz);
                curSeg = g1;   // everything in this tile already flushed
            }
        }

        // final flush of rotated accumulators
        {
            float x  = (rot == 0) ? s0 : ((rot == 1) ? s2 : s1);
            float y  = (rot == 0) ? s1 : ((rot == 1) ? s0 : s2);
            float z  = (rot == 0) ? s2 : ((rot == 1) ? s1 : s0);
            float wx = (rot == 0) ? w0 : ((rot == 1) ? w2 : w1);
            float wy = (rot == 0) ? w1 : ((rot == 1) ? w0 : w2);
            float wz = (rot == 0) ? w2 : ((rot == 1) ? w1 : w0);
            warp_reduce6(wx, wy, wz, x, y, z);
            if (lane == 0) atomic6(curSeg, wx, wy, wz, x, y, z);
        }

        // tail nodes (< 128): per-lane scalar with running flush
        if (tailBeg < end) {
            int   cur = -1;
            float ax = 0.f, ay = 0.f, az = 0.f, rx = 0.f, ry = 0.f, rz = 0.f;
            for (long long i = tailBeg + lane; i < end; i += 32) {
                int   g  = batch[i];
                float qi = q[i];
                float x1 = pos[i * 3 + 0], y1 = pos[i * 3 + 1], z1 = pos[i * 3 + 2];
                if (g != cur) {
                    if (cur >= 0) atomic6(cur, ax, ay, az, rx, ry, rz);
                    ax = ay = az = rx = ry = rz = 0.f;
                    cur = g;
                }
                qs += qi;
                ax = fmaf(qi, x1, ax); ay = fmaf(qi, y1, ay); az = fmaf(qi, z1, az);
                rx += x1; ry += y1; rz += z1;
            }
            if (cur >= 0) atomic6(cur, ax, ay, az, rx, ry, rz);
        }
    }

    // ---- block reduction of qs, one double atomic per block ----
    __shared__ float sm[NWARPS_BLK];
    __shared__ bool  isLast;
    #pragma unroll
    for (int s = 16; s > 0; s >>= 1) qs += __shfl_down_sync(0xffffffffu, qs, s);
    if (lane == 0) sm[w] = qs;
    __syncthreads();
    if (threadIdx.x == 0) {
        float t = 0.f;
        #pragma unroll
        for (int i = 0; i < NWARPS_BLK; i++) t += sm[i];
        atomicAdd(&g_sumq, (double)t);
        __threadfence();
        unsigned int done = atomicAdd(&g_count, 1u);
        isLast = (done == (unsigned int)(gridDim.x - 1));
    }
    __syncthreads();

    // ---- last block: finalize + reset scratch for next graph replay ----
    if (isLast) {
        __threadfence();
        float mean = (float)(g_sumq * inv_n);
        for (int i = threadIdx.x; i < NUM_GRAPHS * 3; i += TPB) {
            out[i]   = g_Sqr[i] - mean * g_Sr[i];
            g_Sqr[i] = 0.0f;
            g_Sr[i]  = 0.0f;
        }
        __syncthreads();
        if (threadIdx.x == 0) {
            g_sumq = 0.0;
            __threadfence();
            g_count = 0u;
        }
    }
}

extern "C" void kernel_launch(void* const* d_in, const int* in_sizes, int n_in,
                              void* d_out, int out_size) {
    const float* pos   = (const float*)d_in[0];
    const float* q     = (const float*)d_in[1];
    const int*   batch = (const int*)d_in[2];
    float*       out   = (float*)d_out;

    long long n = in_sizes[1];

    long long totalWarps = (long long)NBLOCKS * TPB / 32;
    long long chunk = ((n + totalWarps - 1) / totalWarps + 3) & ~3LL;  // multiple of 4

    polar_fused<<<NBLOCKS, TPB>>>(pos, q, batch, out, n, chunk, 1.0 / (double)n);
}

// round 12
// speedup vs baseline: 1.3886x; 1.3886x over previous
#include <cuda_runtime.h>

#define NUM_GRAPHS 1024
#define TPB 256
#define NBLOCKS 2048   // 16384 warps; chunk = n/16384 = 512 for n = 8.4M

__device__ float  g_Sqr[NUM_GRAPHS * 3];   // sum q_i * r_i   (zero-init on load)
__device__ float  g_Sr[NUM_GRAPHS * 3];    // sum r_i         (zero-init on load)
__device__ double g_sumq;                  // sum q_i         (zero-init on load)

__device__ __forceinline__ void warp_reduce6(float& a0, float& a1, float& a2,
                                             float& a3, float& a4, float& a5) {
    #pragma unroll
    for (int s = 16; s > 0; s >>= 1) {
        a0 += __shfl_down_sync(0xffffffffu, a0, s);
        a1 += __shfl_down_sync(0xffffffffu, a1, s);
        a2 += __shfl_down_sync(0xffffffffu, a2, s);
        a3 += __shfl_down_sync(0xffffffffu, a3, s);
        a4 += __shfl_down_sync(0xffffffffu, a4, s);
        a5 += __shfl_down_sync(0xffffffffu, a5, s);
    }
}

__device__ __forceinline__ void atomic6(int seg,
                                        float ax, float ay, float az,
                                        float rx, float ry, float rz) {
    atomicAdd(&g_Sqr[seg * 3 + 0], ax);
    atomicAdd(&g_Sqr[seg * 3 + 1], ay);
    atomicAdd(&g_Sqr[seg * 3 + 2], az);
    atomicAdd(&g_Sr[seg * 3 + 0], rx);
    atomicAdd(&g_Sr[seg * 3 + 1], ry);
    atomicAdd(&g_Sr[seg * 3 + 2], rz);
}

__global__ void polar_main(const float* __restrict__ pos,
                           const float* __restrict__ q,
                           const int* __restrict__ batch,
                           long long n, long long chunk) {
    const int lane = threadIdx.x & 31;
    const long long warpId = ((long long)blockIdx.x * blockDim.x + threadIdx.x) >> 5;
    const long long start  = warpId * chunk;

    float qs = 0.f;

    if (start < n) {
        long long end = start + chunk; if (end > n) end = n;
        const long long nE = end - start;
        const long long nG = nE >> 2;        // full 4-element groups
        const int       r  = (int)(nE & 3);  // tail elements

        const int segFirst = batch[start];
        const int segLast  = batch[end - 1];

        // start is a multiple of 4 -> q+start 16B aligned, pos+start*3 48B aligned
        const float4* q4 = reinterpret_cast<const float4*>(q + start);
        const float4* p4 = reinterpret_cast<const float4*>(pos + start * 3);

        float ax = 0.f, ay = 0.f, az = 0.f, rx = 0.f, ry = 0.f, rz = 0.f;

        if (segFirst == segLast) {
            // ---- fast path (94% of warps): one segment, no batch loads ----
            #pragma unroll 4
            for (long long c = lane; c < nG; c += 32) {
                float4 qv = q4[c];
                float4 pa = p4[3 * c + 0];
                float4 pb = p4[3 * c + 1];
                float4 pc = p4[3 * c + 2];
                qs += (qv.x + qv.y) + (qv.z + qv.w);
                ax = fmaf(qv.x, pa.x, ax); ax = fmaf(qv.y, pa.w, ax);
                ax = fmaf(qv.z, pb.z, ax); ax = fmaf(qv.w, pc.y, ax);
                ay = fmaf(qv.x, pa.y, ay); ay = fmaf(qv.y, pb.x, ay);
                ay = fmaf(qv.z, pb.w, ay); ay = fmaf(qv.w, pc.z, ay);
                az = fmaf(qv.x, pa.z, az); az = fmaf(qv.y, pb.y, az);
                az = fmaf(qv.z, pc.x, az); az = fmaf(qv.w, pc.w, az);
                rx += (pa.x + pa.w) + (pb.z + pc.y);
                ry += (pa.y + pb.x) + (pb.w + pc.z);
                rz += (pa.z + pb.y) + (pc.x + pc.w);
            }
            if (lane < r) {
                long long i = start + (nG << 2) + lane;
                float qi = q[i];
                float x = pos[i * 3 + 0], y = pos[i * 3 + 1], z = pos[i * 3 + 2];
                qs += qi;
                ax = fmaf(qi, x, ax); ay = fmaf(qi, y, ay); az = fmaf(qi, z, az);
                rx += x; ry += y; rz += z;
            }
            warp_reduce6(ax, ay, az, rx, ry, rz);
            if (lane == 0) atomic6(segFirst, ax, ay, az, rx, ry, rz);
        } else {
            // ---- mixed path (~6% of warps): running-segment, flush on change ----
            const int4* b4 = reinterpret_cast<const int4*>(batch + start);
            int cur = -1;

            #pragma unroll 2
            for (long long c = lane; c < nG; c += 32) {
                float4 qv = q4[c];
                int4   gv = b4[c];
                float4 pa = p4[3 * c + 0];
                float4 pb = p4[3 * c + 1];
                float4 pc = p4[3 * c + 2];
                int   g[4]  = {gv.x, gv.y, gv.z, gv.w};
                float qq[4] = {qv.x, qv.y, qv.z, qv.w};
                float px[4] = {pa.x, pa.w, pb.z, pc.y};
                float py[4] = {pa.y, pb.x, pb.w, pc.z};
                float pz[4] = {pa.z, pb.y, pc.x, pc.w};
                #pragma unroll
                for (int m = 0; m < 4; m++) {
                    if (g[m] != cur) {
                        if (cur >= 0) atomic6(cur, ax, ay, az, rx, ry, rz);
                        ax = ay = az = rx = ry = rz = 0.f;
                        cur = g[m];
                    }
                    qs += qq[m];
                    ax = fmaf(qq[m], px[m], ax);
                    ay = fmaf(qq[m], py[m], ay);
                    az = fmaf(qq[m], pz[m], az);
                    rx += px[m]; ry += py[m]; rz += pz[m];
                }
            }
            if (lane < r) {
                long long i = start + (nG << 2) + lane;
                int   g  = batch[i];
                float qi = q[i];
                float x = pos[i * 3 + 0], y = pos[i * 3 + 1], z = pos[i * 3 + 2];
                if (g != cur) {
                    if (cur >= 0) atomic6(cur, ax, ay, az, rx, ry, rz);
                    ax = ay = az = rx = ry = rz = 0.f;
                    cur = g;
                }
                qs += qi;
                ax = fmaf(qi, x, ax); ay = fmaf(qi, y, ay); az = fmaf(qi, z, az);
                rx += x; ry += y; rz += z;
            }
            if (cur >= 0) atomic6(cur, ax, ay, az, rx, ry, rz);
        }
    }

    // ---- qs reduction: warp shfl, then one double atomic per block ----
    __shared__ float sm[TPB / 32];
    #pragma unroll
    for (int s = 16; s > 0; s >>= 1) qs += __shfl_down_sync(0xffffffffu, qs, s);
    if (lane == 0) sm[threadIdx.x >> 5] = qs;
    __syncthreads();
    if (threadIdx.x == 0) {
        float t = 0.f;
        #pragma unroll
        for (int i = 0; i < TPB / 32; i++) t += sm[i];
        atomicAdd(&g_sumq, (double)t);
    }
}

// Single block: writes output, then resets all scratch for the next graph
// replay (first call starts clean via static zero-init). __syncthreads()
// orders every read of g_sumq before its reset.
__global__ void finalize_kernel(float* out, double inv_n) {
    float mean = (float)(g_sumq * inv_n);
    for (int i = threadIdx.x; i < NUM_GRAPHS * 3; i += blockDim.x) {
        out[i]   = g_Sqr[i] - mean * g_Sr[i];
        g_Sqr[i] = 0.0f;
        g_Sr[i]  = 0.0f;
    }
    __syncthreads();
    if (threadIdx.x == 0) g_sumq = 0.0;
}

extern "C" void kernel_launch(void* const* d_in, const int* in_sizes, int n_in,
                              void* d_out, int out_size) {
    const float* pos   = (const float*)d_in[0];
    const float* q     = (const float*)d_in[1];
    const int*   batch = (const int*)d_in[2];
    float*       out   = (float*)d_out;

    long long n = in_sizes[1];

    long long totalWarps = (long long)NBLOCKS * TPB / 32;
    long long chunk = ((n + totalWarps - 1) / totalWarps + 3) & ~3LL;  // multiple of 4

    polar_main<<<NBLOCKS, TPB>>>(pos, q, batch, n, chunk);
    finalize_kernel<<<1, 1024>>>(out, 1.0 / (double)n);
}

// round 13
// speedup vs baseline: 1.4545x; 1.0475x over previous
#include <cuda_runtime.h>

#define NUM_GRAPHS 1024
#define TPB 256
#define NBLOCKS 1024    // 8192 warps; chunk = 1024 (proven best granularity)
#define NWARPS (TPB / 32)

__device__ float        g_Sqr[NUM_GRAPHS * 3];   // sum q_i * r_i (zero-init)
__device__ float        g_Sr[NUM_GRAPHS * 3];    // sum r_i       (zero-init)
__device__ double       g_sumq;                  // sum q_i       (zero-init)
__device__ unsigned int g_count;                 // finalize rendezvous

__device__ __forceinline__ void warp_reduce6(float& a0, float& a1, float& a2,
                                             float& a3, float& a4, float& a5) {
    #pragma unroll
    for (int s = 16; s > 0; s >>= 1) {
        a0 += __shfl_down_sync(0xffffffffu, a0, s);
        a1 += __shfl_down_sync(0xffffffffu, a1, s);
        a2 += __shfl_down_sync(0xffffffffu, a2, s);
        a3 += __shfl_down_sync(0xffffffffu, a3, s);
        a4 += __shfl_down_sync(0xffffffffu, a4, s);
        a5 += __shfl_down_sync(0xffffffffu, a5, s);
    }
}

__device__ __forceinline__ void atomic6(int seg,
                                        float ax, float ay, float az,
                                        float rx, float ry, float rz) {
    atomicAdd(&g_Sqr[seg * 3 + 0], ax);
    atomicAdd(&g_Sqr[seg * 3 + 1], ay);
    atomicAdd(&g_Sqr[seg * 3 + 2], az);
    atomicAdd(&g_Sr[seg * 3 + 0], rx);
    atomicAdd(&g_Sr[seg * 3 + 1], ry);
    atomicAdd(&g_Sr[seg * 3 + 2], rz);
}

__global__ __launch_bounds__(TPB)
void polar_main(const float* __restrict__ pos,
                const float* __restrict__ q,
                const int* __restrict__ batch,
                long long n, long long chunk) {
    // per-warp double-buffered pos staging: 96 float4 = 1536B per buffer
    __shared__ float4 stage[NWARPS][2][96];

    const int lane = threadIdx.x & 31;
    const int w    = threadIdx.x >> 5;
    const long long warpId = ((long long)blockIdx.x * blockDim.x + threadIdx.x) >> 5;
    const long long start  = warpId * chunk;

    float qs = 0.f;

    if (start < n) {
        long long end = start + chunk; if (end > n) end = n;
        const long long nE      = end - start;
        const long long nTiles  = nE >> 7;               // full 128-node tiles
        const long long tailBeg = start + (nTiles << 7);

        const int segFirst = batch[start];
        const int segLast  = batch[end - 1];

        // start is a multiple of 4 -> all bases 16B aligned
        const float4* q4 = reinterpret_cast<const float4*>(q + start);
        const float4* p4 = reinterpret_cast<const float4*>(pos + start * 3);

        float ax = 0.f, ay = 0.f, az = 0.f, rx = 0.f, ry = 0.f, rz = 0.f;

        if (segFirst == segLast) {
            // ---- fast path: one segment; coalesced LDG -> smem -> strided LDS ----
            float4 qv, PA, PB, PC;
            if (nTiles > 0) {                       // preload tile 0
                qv = q4[lane];
                PA = p4[lane]; PB = p4[32 + lane]; PC = p4[64 + lane];
            }
            for (long long j = 0; j < nTiles; j++) {
                float4* buf = stage[w][j & 1];
                buf[lane] = PA; buf[32 + lane] = PB; buf[64 + lane] = PC;
                float4 qc = qv;
                if (j + 1 < nTiles) {               // pipeline next tile's loads
                    qv = q4[((j + 1) << 5) + lane];
                    PA = p4[(j + 1) * 96 + lane];
                    PB = p4[(j + 1) * 96 + 32 + lane];
                    PC = p4[(j + 1) * 96 + 64 + lane];
                }
                __syncwarp();
                // conflict-free: 48B lane stride partitions banks per 8-lane phase
                float4 pa = buf[3 * lane + 0];
                float4 pb = buf[3 * lane + 1];
                float4 pc = buf[3 * lane + 2];
                __syncwarp();                       // LDS done before next STS (WAR)

                qs += (qc.x + qc.y) + (qc.z + qc.w);
                ax = fmaf(qc.x, pa.x, ax); ax = fmaf(qc.y, pa.w, ax);
                ax = fmaf(qc.z, pb.z, ax); ax = fmaf(qc.w, pc.y, ax);
                ay = fmaf(qc.x, pa.y, ay); ay = fmaf(qc.y, pb.x, ay);
                ay = fmaf(qc.z, pb.w, ay); ay = fmaf(qc.w, pc.z, ay);
                az = fmaf(qc.x, pa.z, az); az = fmaf(qc.y, pb.y, az);
                az = fmaf(qc.z, pc.x, az); az = fmaf(qc.w, pc.w, az);
                rx += (pa.x + pa.w) + (pb.z + pc.y);
                ry += (pa.y + pb.x) + (pb.w + pc.z);
                rz += (pa.z + pb.y) + (pc.x + pc.w);
            }
            // tail (< 128 nodes, all segFirst): per-lane scalar
            for (long long i = tailBeg + lane; i < end; i += 32) {
                float qi = q[i];
                float x = pos[i * 3 + 0], y = pos[i * 3 + 1], z = pos[i * 3 + 2];
                qs += qi;
                ax = fmaf(qi, x, ax); ay = fmaf(qi, y, ay); az = fmaf(qi, z, az);
                rx += x; ry += y; rz += z;
            }
            warp_reduce6(ax, ay, az, rx, ry, rz);
            if (lane == 0) atomic6(segFirst, ax, ay, az, rx, ry, rz);
        } else {
            // ---- mixed path (~12% of warps): same staging + per-node flush ----
            const int4* b4 = reinterpret_cast<const int4*>(batch + start);
            int cur = -1;

            for (long long j = 0; j < nTiles; j++) {
                float4 qv = q4[(j << 5) + lane];
                int4   gv = b4[(j << 5) + lane];     // own 4 nodes' segments
                float4* buf = stage[w][j & 1];
                buf[lane]      = p4[j * 96 + lane];
                buf[32 + lane] = p4[j * 96 + 32 + lane];
                buf[64 + lane] = p4[j * 96 + 64 + lane];
                __syncwarp();
                float4 pa = buf[3 * lane + 0];
                float4 pb = buf[3 * lane + 1];
                float4 pc = buf[3 * lane + 2];
                __syncwarp();

                int   g[4]  = {gv.x, gv.y, gv.z, gv.w};
                float qq[4] = {qv.x, qv.y, qv.z, qv.w};
                float px[4] = {pa.x, pa.w, pb.z, pc.y};
                float py[4] = {pa.y, pb.x, pb.w, pc.z};
                float pz[4] = {pa.z, pb.y, pc.x, pc.w};
                #pragma unroll
                for (int m = 0; m < 4; m++) {
                    if (g[m] != cur) {
                        if (cur >= 0) atomic6(cur, ax, ay, az, rx, ry, rz);
                        ax = ay = az = rx = ry = rz = 0.f;
                        cur = g[m];
                    }
                    qs += qq[m];
                    ax = fmaf(qq[m], px[m], ax);
                    ay = fmaf(qq[m], py[m], ay);
                    az = fmaf(qq[m], pz[m], az);
                    rx += px[m]; ry += py[m]; rz += pz[m];
                }
            }
            // tail nodes: per-lane scalar running flush
            for (long long i = tailBeg + lane; i < end; i += 32) {
                int   g  = batch[i];
                float qi = q[i];
                float x = pos[i * 3 + 0], y = pos[i * 3 + 1], z = pos[i * 3 + 2];
                if (g != cur) {
                    if (cur >= 0) atomic6(cur, ax, ay, az, rx, ry, rz);
                    ax = ay = az = rx = ry = rz = 0.f;
                    cur = g;
                }
                qs += qi;
                ax = fmaf(qi, x, ax); ay = fmaf(qi, y, ay); az = fmaf(qi, z, az);
                rx += x; ry += y; rz += z;
            }
            if (cur >= 0) atomic6(cur, ax, ay, az, rx, ry, rz);
        }
    }

    // ---- qs reduction: warp shfl, then one double atomic per block ----
    __shared__ float sm[NWARPS];
    #pragma unroll
    for (int s = 16; s > 0; s >>= 1) qs += __shfl_down_sync(0xffffffffu, qs, s);
    if (lane == 0) sm[w] = qs;
    __syncthreads();
    if (threadIdx.x == 0) {
        float t = 0.f;
        #pragma unroll
        for (int i = 0; i < NWARPS; i++) t += sm[i];
        atomicAdd(&g_sumq, (double)t);
    }
}

// Multi-block finalize. Every thread reads g_sumq BEFORE its block arrives at
// the counter; the last-arriving block resets g_sumq/g_count, so the reset is
// ordered after all reads. Scratch zeroing readies the next graph replay.
__global__ void finalize_kernel(float* out, double inv_n) {
    const int i = blockIdx.x * blockDim.x + threadIdx.x;
    const float mean = (float)(g_sumq * inv_n);     // read first
    if (i < NUM_GRAPHS * 3) {
        out[i]   = g_Sqr[i] - mean * g_Sr[i];
        g_Sqr[i] = 0.0f;
        g_Sr[i]  = 0.0f;
    }
    __syncthreads();                                 // all reads in block done
    if (threadIdx.x == 0) {
        __threadfence();
        unsigned int done = atomicAdd(&g_count, 1u);
        if (done == gridDim.x - 1) {                 // last block: safe to reset
            g_sumq  = 0.0;
            __threadfence();
            g_count = 0u;
        }
    }
}

extern "C" void kernel_launch(void* const* d_in, const int* in_sizes, int n_in,
                              void* d_out, int out_size) {
    const float* pos   = (const float*)d_in[0];
    const float* q     = (const float*)d_in[1];
    const int*   batch = (const int*)d_in[2];
    float*       out   = (float*)d_out;

    long long n = in_sizes[1];

    long long totalWarps = (long long)NBLOCKS * TPB / 32;
    long long chunk = ((n + totalWarps - 1) / totalWarps + 3) & ~3LL;  // mult of 4

    polar_main<<<NBLOCKS, TPB>>>(pos, q, batch, n, chunk);
    finalize_kernel<<<(NUM_GRAPHS * 3 + TPB - 1) / TPB, TPB>>>(out, 1.0 / (double)n);
}

// round 14
// speedup vs baseline: 1.8506x; 1.2723x over previous
#include <cuda_runtime.h>

#define NUM_GRAPHS 1024
#define TPB 256
#define NBLOCKS 1024   // 8192 warps -> chunk = 1024 (proven best, R5)

__device__ float        g_Sqr[NUM_GRAPHS * 3];   // sum q_i * r_i (zero-init)
__device__ float        g_Sr[NUM_GRAPHS * 3];    // sum r_i       (zero-init)
__device__ double       g_sumq;                  // sum q_i       (zero-init)
__device__ unsigned int g_count;                 // finalize rendezvous

__device__ __forceinline__ void warp_reduce6(float& a0, float& a1, float& a2,
                                             float& a3, float& a4, float& a5) {
    #pragma unroll
    for (int s = 16; s > 0; s >>= 1) {
        a0 += __shfl_down_sync(0xffffffffu, a0, s);
        a1 += __shfl_down_sync(0xffffffffu, a1, s);
        a2 += __shfl_down_sync(0xffffffffu, a2, s);
        a3 += __shfl_down_sync(0xffffffffu, a3, s);
        a4 += __shfl_down_sync(0xffffffffu, a4, s);
        a5 += __shfl_down_sync(0xffffffffu, a5, s);
    }
}

__device__ __forceinline__ void atomic6(int seg,
                                        float ax, float ay, float az,
                                        float rx, float ry, float rz) {
    atomicAdd(&g_Sqr[seg * 3 + 0], ax);
    atomicAdd(&g_Sqr[seg * 3 + 1], ay);
    atomicAdd(&g_Sqr[seg * 3 + 2], az);
    atomicAdd(&g_Sr[seg * 3 + 0], rx);
    atomicAdd(&g_Sr[seg * 3 + 1], ry);
    atomicAdd(&g_Sr[seg * 3 + 2], rz);
}

__global__ void polar_main(const float* __restrict__ pos,
                           const float* __restrict__ q,
                           const int* __restrict__ batch,
                           long long n, long long chunk) {
    const int lane = threadIdx.x & 31;
    const long long warpId = ((long long)blockIdx.x * blockDim.x + threadIdx.x) >> 5;
    const long long start  = warpId * chunk;

    float qs = 0.f;

    if (start < n) {
        long long end = start + chunk; if (end > n) end = n;
        const long long nE = end - start;
        const long long nG = nE >> 2;        // full 4-element groups
        const int       r  = (int)(nE & 3);  // tail elements

        const int segFirst = batch[start];
        const int segLast  = batch[end - 1];

        // start is a multiple of 4 -> q+start is 16B aligned, pos+start*3 is 48B aligned
        const float4* q4 = reinterpret_cast<const float4*>(q + start);
        const float4* p4 = reinterpret_cast<const float4*>(pos + start * 3);

        float ax = 0.f, ay = 0.f, az = 0.f, rx = 0.f, ry = 0.f, rz = 0.f;

        if (segFirst == segLast) {
            // ---- fast path: whole chunk is one segment; no batch loads ----
            #pragma unroll 4
            for (long long c = lane; c < nG; c += 32) {
                float4 qv = q4[c];
                float4 pa = p4[3 * c + 0];
                float4 pb = p4[3 * c + 1];
                float4 pc = p4[3 * c + 2];
                qs += (qv.x + qv.y) + (qv.z + qv.w);
                ax = fmaf(qv.x, pa.x, ax); ax = fmaf(qv.y, pa.w, ax);
                ax = fmaf(qv.z, pb.z, ax); ax = fmaf(qv.w, pc.y, ax);
                ay = fmaf(qv.x, pa.y, ay); ay = fmaf(qv.y, pb.x, ay);
                ay = fmaf(qv.z, pb.w, ay); ay = fmaf(qv.w, pc.z, ay);
                az = fmaf(qv.x, pa.z, az); az = fmaf(qv.y, pb.y, az);
                az = fmaf(qv.z, pc.x, az); az = fmaf(qv.w, pc.w, az);
                rx += (pa.x + pa.w) + (pb.z + pc.y);
                ry += (pa.y + pb.x) + (pb.w + pc.z);
                rz += (pa.z + pb.y) + (pc.x + pc.w);
            }
            if (lane < r) {
                long long i = start + (nG << 2) + lane;
                float qi = q[i];
                float x = pos[i * 3 + 0], y = pos[i * 3 + 1], z = pos[i * 3 + 2];
                qs += qi;
                ax = fmaf(qi, x, ax); ay = fmaf(qi, y, ay); az = fmaf(qi, z, az);
                rx += x; ry += y; rz += z;
            }
            warp_reduce6(ax, ay, az, rx, ry, rz);
            if (lane == 0) atomic6(segFirst, ax, ay, az, rx, ry, rz);
        } else {
            // ---- mixed path (~12% of warps): dual predicated accumulators ----
            const int4* b4 = reinterpret_cast<const int4*>(batch + start);
            float bx = 0.f, by = 0.f, bz = 0.f, sx = 0.f, sy = 0.f, sz = 0.f;

            #pragma unroll 2
            for (long long c = lane; c < nG; c += 32) {
                float4 qv = q4[c];
                int4   gv = b4[c];
                float4 pa = p4[3 * c + 0];
                float4 pb = p4[3 * c + 1];
                float4 pc = p4[3 * c + 2];
                int   g[4]  = {gv.x, gv.y, gv.z, gv.w};
                float qq[4] = {qv.x, qv.y, qv.z, qv.w};
                float px[4] = {pa.x, pa.w, pb.z, pc.y};
                float py[4] = {pa.y, pb.x, pb.w, pc.z};
                float pz[4] = {pa.z, pb.y, pc.x, pc.w};
                #pragma unroll
                for (int m = 0; m < 4; m++) {
                    qs += qq[m];
                    if (g[m] == segFirst) {
                        ax = fmaf(qq[m], px[m], ax); ay = fmaf(qq[m], py[m], ay);
                        az = fmaf(qq[m], pz[m], az);
                        rx += px[m]; ry += py[m]; rz += pz[m];
                    } else if (g[m] == segLast) {
                        bx = fmaf(qq[m], px[m], bx); by = fmaf(qq[m], py[m], by);
                        bz = fmaf(qq[m], pz[m], bz);
                        sx += px[m]; sy += py[m]; sz += pz[m];
                    } else {
                        atomic6(g[m], qq[m] * px[m], qq[m] * py[m],
                                qq[m] * pz[m], px[m], py[m], pz[m]);
                    }
                }
            }
            if (lane < r) {
                long long i = start + (nG << 2) + lane;
                int   g  = batch[i];
                float qi = q[i];
                float x = pos[i * 3 + 0], y = pos[i * 3 + 1], z = pos[i * 3 + 2];
                qs += qi;
                if (g == segFirst) {
                    ax = fmaf(qi, x, ax); ay = fmaf(qi, y, ay); az = fmaf(qi, z, az);
                    rx += x; ry += y; rz += z;
                } else if (g == segLast) {
                    bx = fmaf(qi, x, bx); by = fmaf(qi, y, by); bz = fmaf(qi, z, bz);
                    sx += x; sy += y; sz += z;
                } else {
                    atomic6(g, qi * x, qi * y, qi * z, x, y, z);
                }
            }
            warp_reduce6(ax, ay, az, rx, ry, rz);
            warp_reduce6(bx, by, bz, sx, sy, sz);
            if (lane == 0) {
                atomic6(segFirst, ax, ay, az, rx, ry, rz);
                atomic6(segLast,  bx, by, bz, sx, sy, sz);
            }
        }
    }

    // ---- block-level reduction of qs, then one double atomic per block ----
    __shared__ float sm[TPB];
    sm[threadIdx.x] = qs;
    __syncthreads();
    #pragma unroll
    for (int s = TPB / 2; s > 0; s >>= 1) {
        if (threadIdx.x < s) sm[threadIdx.x] += sm[threadIdx.x + s];
        __syncthreads();
    }
    if (threadIdx.x == 0) atomicAdd(&g_sumq, (double)sm[0]);
}

// Multi-block finalize. Every thread reads g_sumq BEFORE its block arrives at
// the counter; the last-arriving block resets g_sumq/g_count, so the reset is
// ordered after all reads. Scratch zeroing readies the next graph replay
// (first call starts clean via static zero-init).
__global__ void finalize_kernel(float* out, double inv_n) {
    const int i = blockIdx.x * blockDim.x + threadIdx.x;
    const float mean = (float)(g_sumq * inv_n);     // read first
    if (i < NUM_GRAPHS * 3) {
        out[i]   = g_Sqr[i] - mean * g_Sr[i];
        g_Sqr[i] = 0.0f;
        g_Sr[i]  = 0.0f;
    }
    __syncthreads();                                 // all reads in block done
    if (threadIdx.x == 0) {
        __threadfence();
        unsigned int done = atomicAdd(&g_count, 1u);
        if (done == gridDim.x - 1) {                 // last block: safe to reset
            g_sumq  = 0.0;
            __threadfence();
            g_count = 0u;
        }
    }
}

extern "C" void kernel_launch(void* const* d_in, const int* in_sizes, int n_in,
                              void* d_out, int out_size) {
    const float* pos   = (const float*)d_in[0];
    const float* q     = (const float*)d_in[1];
    const int*   batch = (const int*)d_in[2];
    float*       out   = (float*)d_out;

    long long n = in_sizes[1];

    long long totalWarps = (long long)NBLOCKS * TPB / 32;
    long long chunk = ((n + totalWarps - 1) / totalWarps + 3) & ~3LL;  // mult of 4

    polar_main<<<NBLOCKS, TPB>>>(pos, q, batch, n, chunk);
    finalize_kernel<<<(NUM_GRAPHS * 3 + TPB - 1) / TPB, TPB>>>(out, 1.0 / (double)n);
}